// round 9
// baseline (speedup 1.0000x reference)
#include <cuda_runtime.h>
#include <cuda_bf16.h>
#include <cstdint>

#define BATCH 8
#define CH    512
#define NSP   4096
#define CH2   (CH * 2)

// ---------------- global scratch, all hi/lo K-packed ----------------
// packed row layout: [k/64 chunk][hi 64 | lo 64] bf16  (128 elems = 256B per chunk)
__device__ __align__(16) __nv_bfloat16 g_w   [(size_t)3 * CH * CH2];
__device__ __align__(16) __nv_bfloat16 g_xt  [(size_t)BATCH * NSP * CH2];
__device__ __align__(16) __nv_bfloat16 g_q   [(size_t)BATCH * CH * (NSP * 2)];
__device__ __align__(16) __nv_bfloat16 g_k   [(size_t)BATCH * CH * (NSP * 2)];
__device__ __align__(16) __nv_bfloat16 g_vt  [(size_t)BATCH * NSP * CH2];
__device__ __align__(16) __nv_bfloat16 g_attn_p[(size_t)BATCH * CH * CH2];
__device__ __align__(16) float         g_attn_raw[(size_t)BATCH * CH * CH];

// ---------------- low-level helpers ----------------
__device__ __forceinline__ uint32_t smem_u32(const void* p) {
    uint32_t a;
    asm("{ .reg .u64 t; cvta.to.shared.u64 t, %1; cvt.u32.u64 %0, t; }" : "=r"(a) : "l"(p));
    return a;
}
__device__ __forceinline__ void cp16(uint32_t s, const void* g) {
    asm volatile("cp.async.cg.shared.global [%0], [%1], 16;" :: "r"(s), "l"(g));
}
__device__ __forceinline__ void ldsm4(uint32_t* r, uint32_t addr) {
    asm volatile("ldmatrix.sync.aligned.m8n8.x4.shared.b16 {%0,%1,%2,%3}, [%4];"
                 : "=r"(r[0]), "=r"(r[1]), "=r"(r[2]), "=r"(r[3]) : "r"(addr));
}
__device__ __forceinline__ void mma16816(float* d, const uint32_t* a, const uint32_t* b) {
    asm volatile("mma.sync.aligned.m16n8k16.row.col.f32.bf16.bf16.f32 "
                 "{%0,%1,%2,%3}, {%4,%5,%6,%7}, {%8,%9}, {%0,%1,%2,%3};"
                 : "+f"(d[0]), "+f"(d[1]), "+f"(d[2]), "+f"(d[3])
                 : "r"(a[0]), "r"(a[1]), "r"(a[2]), "r"(a[3]), "r"(b[0]), "r"(b[1]));
}
__device__ __forceinline__ void split2(float f, __nv_bfloat16& h, __nv_bfloat16& l) {
    h = __float2bfloat16(f);
    l = __float2bfloat16(f - __bfloat162float(h));
}

// Load a 128-row x 256B chunk tile (32KB) with XOR-8 swizzle on 16B units.
__device__ __forceinline__ void load_tile128(uint32_t sdst, const __nv_bfloat16* gsrc,
                                             size_t rowlen, int tid) {
    #pragma unroll
    for (int i = 0; i < 8; i++) {
        int idx = tid + i * 256;
        int r = idx >> 4, u = idx & 15;
        cp16(sdst + r * 256 + ((u ^ (r & 7)) * 16),
             gsrc + (size_t)r * rowlen + u * 8);
    }
}
// Load a 256-row x 256B chunk tile (64KB).
__device__ __forceinline__ void load_tile256(uint32_t sdst, const __nv_bfloat16* gsrc,
                                             size_t rowlen, int tid) {
    #pragma unroll
    for (int i = 0; i < 16; i++) {
        int idx = tid + i * 256;
        int r = idx >> 4, u = idx & 15;
        cp16(sdst + r * 256 + ((u ^ (r & 7)) * 16),
             gsrc + (size_t)r * rowlen + u * 8);
    }
}

// ============ core A: 128x128 tile (attn), 3-stage, warp tile 64x32 ============
__device__ __forceinline__ void gemm_core128(const __nv_bfloat16* __restrict__ Ag,
                                             const __nv_bfloat16* __restrict__ Bg,
                                             int nch, size_t lda, size_t ldb,
                                             float (&acc)[4][4][4]) {
    extern __shared__ char smem[];
    const uint32_t sb = smem_u32(smem);
    const int tid = threadIdx.x;
    const int lane = tid & 31, w = tid >> 5;
    const int wm = (w >> 2) * 64, wn = (w & 3) * 32;

    #pragma unroll
    for (int i = 0; i < 4; i++)
        #pragma unroll
        for (int j = 0; j < 4; j++)
            #pragma unroll
            for (int r = 0; r < 4; r++) acc[i][j][r] = 0.f;

    load_tile128(sb,         Ag, lda, tid);
    load_tile128(sb + 32768, Bg, ldb, tid);
    asm volatile("cp.async.commit_group;" ::: "memory");
    load_tile128(sb + 65536, Ag + 128, lda, tid);
    load_tile128(sb + 98304, Bg + 128, ldb, tid);
    asm volatile("cp.async.commit_group;" ::: "memory");

    for (int ch = 0; ch < nch; ch++) {
        asm volatile("cp.async.wait_group 1;" ::: "memory");
        __syncthreads();
        if (ch + 2 < nch) {
            const uint32_t st = sb + ((ch + 2) % 3) * 65536;
            load_tile128(st,         Ag + (size_t)(ch + 2) * 128, lda, tid);
            load_tile128(st + 32768, Bg + (size_t)(ch + 2) * 128, ldb, tid);
        }
        asm volatile("cp.async.commit_group;" ::: "memory");

        const uint32_t s_a = sb + (ch % 3) * 65536;
        const uint32_t s_b = s_a + 32768;
        #pragma unroll
        for (int ks = 0; ks < 4; ks++) {
            uint32_t ah[4][4], al[4][4], bh[2][4], bl[2][4];
            #pragma unroll
            for (int i = 0; i < 4; i++) {
                int r = wm + 16 * i + (lane & 7) + ((lane >> 3) & 1) * 8;
                int u = 2 * ks + ((lane >> 4) & 1);
                ldsm4(ah[i], s_a + r * 256 + ((u       ^ (r & 7)) * 16));
                ldsm4(al[i], s_a + r * 256 + (((u + 8) ^ (r & 7)) * 16));
            }
            #pragma unroll
            for (int jj = 0; jj < 2; jj++) {
                int r = wn + 16 * jj + (lane & 7) + ((lane >> 4) & 1) * 8;
                int u = 2 * ks + ((lane >> 3) & 1);
                ldsm4(bh[jj], s_b + r * 256 + ((u       ^ (r & 7)) * 16));
                ldsm4(bl[jj], s_b + r * 256 + (((u + 8) ^ (r & 7)) * 16));
            }
            #pragma unroll
            for (int i = 0; i < 4; i++)
                #pragma unroll
                for (int j = 0; j < 4; j++)
                    mma16816(acc[i][j], ah[i], &bh[j >> 1][(j & 1) * 2]);
            #pragma unroll
            for (int i = 0; i < 4; i++)
                #pragma unroll
                for (int j = 0; j < 4; j++)
                    mma16816(acc[i][j], ah[i], &bl[j >> 1][(j & 1) * 2]);
            #pragma unroll
            for (int i = 0; i < 4; i++)
                #pragma unroll
                for (int j = 0; j < 4; j++)
                    mma16816(acc[i][j], al[i], &bh[j >> 1][(j & 1) * 2]);
        }
    }
    asm volatile("cp.async.wait_group 0;" ::: "memory");
    __syncthreads();
}

// ============ core B: 128x256 tile (qkv/out), 2-stage, warp tile 64x64 ============
// A: 128 rows, B: 256 rows. acc[4][8][4] (128 regs). stages: s*98304 = A 32KB | B 64KB
__device__ __forceinline__ void gemm_core256(const __nv_bfloat16* __restrict__ Ag,
                                             const __nv_bfloat16* __restrict__ Bg,
                                             int nch, size_t lda, size_t ldb,
                                             float (&acc)[4][8][4]) {
    extern __shared__ char smem[];
    const uint32_t sb = smem_u32(smem);
    const int tid = threadIdx.x;
    const int lane = tid & 31, w = tid >> 5;
    const int wm = (w >> 2) * 64, wn = (w & 3) * 64;

    #pragma unroll
    for (int i = 0; i < 4; i++)
        #pragma unroll
        for (int j = 0; j < 8; j++)
            #pragma unroll
            for (int r = 0; r < 4; r++) acc[i][j][r] = 0.f;

    load_tile128(sb,         Ag, lda, tid);
    load_tile256(sb + 32768, Bg, ldb, tid);
    asm volatile("cp.async.commit_group;" ::: "memory");
    if (nch > 1) {
        load_tile128(sb + 98304,          Ag + 128, lda, tid);
        load_tile256(sb + 98304 + 32768,  Bg + 128, ldb, tid);
    }
    asm volatile("cp.async.commit_group;" ::: "memory");

    for (int ch = 0; ch < nch; ch++) {
        asm volatile("cp.async.wait_group 1;" ::: "memory");
        __syncthreads();

        const uint32_t s_a = sb + (ch & 1) * 98304;
        const uint32_t s_b = s_a + 32768;
        #pragma unroll
        for (int ks = 0; ks < 4; ks++) {
            uint32_t bh[4][4], bl[4][4];
            #pragma unroll
            for (int jj = 0; jj < 4; jj++) {
                int r = wn + 16 * jj + (lane & 7) + ((lane >> 4) & 1) * 8;
                int u = 2 * ks + ((lane >> 3) & 1);
                ldsm4(bh[jj], s_b + r * 256 + ((u       ^ (r & 7)) * 16));
                ldsm4(bl[jj], s_b + r * 256 + (((u + 8) ^ (r & 7)) * 16));
            }
            #pragma unroll
            for (int i = 0; i < 4; i++) {
                uint32_t ah[4], al[4];
                int r = wm + 16 * i + (lane & 7) + ((lane >> 3) & 1) * 8;
                int u = 2 * ks + ((lane >> 4) & 1);
                ldsm4(ah, s_a + r * 256 + ((u       ^ (r & 7)) * 16));
                ldsm4(al, s_a + r * 256 + (((u + 8) ^ (r & 7)) * 16));
                #pragma unroll
                for (int j = 0; j < 8; j++)
                    mma16816(acc[i][j], ah, &bh[j >> 1][(j & 1) * 2]);
                #pragma unroll
                for (int j = 0; j < 8; j++)
                    mma16816(acc[i][j], ah, &bl[j >> 1][(j & 1) * 2]);
                #pragma unroll
                for (int j = 0; j < 8; j++)
                    mma16816(acc[i][j], al, &bh[j >> 1][(j & 1) * 2]);
            }
        }
        __syncthreads();
        if (ch + 2 < nch) {
            const uint32_t st = sb + (ch & 1) * 98304;
            load_tile128(st,         Ag + (size_t)(ch + 2) * 128, lda, tid);
            load_tile256(st + 32768, Bg + (size_t)(ch + 2) * 128, ldb, tid);
        }
        asm volatile("cp.async.commit_group;" ::: "memory");
    }
    asm volatile("cp.async.wait_group 0;" ::: "memory");
    __syncthreads();
}

// ---------------- kernel 1: QKV projections (128x256 tiles) ----------------
// grid (NSP/256=16, CH/128=4, BATCH*3)
__global__ __launch_bounds__(256, 1) void qkv_gemm(
    const float* __restrict__ bq, const float* __restrict__ bk, const float* __restrict__ bv)
{
    const int z = blockIdx.z;
    const int batch = z / 3, which = z % 3;
    const int c0 = blockIdx.y * 128, n0 = blockIdx.x * 256;

    const __nv_bfloat16* Ag = g_w + (size_t)which * CH * CH2 + (size_t)c0 * CH2;
    const __nv_bfloat16* Bg = g_xt + ((size_t)batch * NSP + n0) * CH2;

    float acc[4][8][4];
    gemm_core256(Ag, Bg, CH / 64, CH2, CH2, acc);

    const float* bias = (which == 0) ? bq : (which == 1) ? bk : bv;
    const int tid = threadIdx.x, lane = tid & 31, w = tid >> 5;
    const int wm = (w >> 2) * 64, wn = (w & 3) * 64;

    if (which < 2) {
        // direct reg->gmem packed store: rows=c, K=n; chunk base constant per warp
        __nv_bfloat16* base = ((which == 0) ? g_q : g_k) + ((size_t)batch * CH) * (NSP * 2);
        const int chunkoff = ((n0 + wn) >> 6) * 128;
        #pragma unroll
        for (int i = 0; i < 4; i++)
            #pragma unroll
            for (int r2 = 0; r2 < 2; r2++) {
                int m = c0 + wm + 16 * i + (lane >> 2) + 8 * r2;
                float bvv = bias[m];
                __nv_bfloat16* dst = base + (size_t)m * (NSP * 2) + chunkoff + 2 * (lane & 3);
                #pragma unroll
                for (int j = 0; j < 8; j++) {
                    float f0 = acc[i][j][2 * r2] + bvv;
                    float f1 = acc[i][j][2 * r2 + 1] + bvv;
                    __nv_bfloat16 h0, l0, h1, l1;
                    split2(f0, h0, l0); split2(f1, h1, l1);
                    uint32_t hp = (uint32_t)__bfloat16_as_ushort(h0)
                                | ((uint32_t)__bfloat16_as_ushort(h1) << 16);
                    uint32_t lp = (uint32_t)__bfloat16_as_ushort(l0)
                                | ((uint32_t)__bfloat16_as_ushort(l1) << 16);
                    *(uint32_t*)(dst + 8 * j)      = hp;
                    *(uint32_t*)(dst + 8 * j + 64) = lp;
                }
            }
    } else {
        // v: transpose via smem (256 n-rows x 128 c-cols), store vt rows=n, K=c
        extern __shared__ char smem[];
        float* smemf = (float*)smem;                   // 256 x 132 floats = 135KB
        #pragma unroll
        for (int i = 0; i < 4; i++)
            #pragma unroll
            for (int j = 0; j < 8; j++)
                #pragma unroll
                for (int r = 0; r < 4; r++) {
                    int m  = wm + 16 * i + (lane >> 2) + 8 * (r >> 1);
                    int nl = wn + 8 * j + 2 * (lane & 3) + (r & 1);
                    smemf[nl * 132 + m] = acc[i][j][r];
                }
        __syncthreads();
        const int chunk = lane >> 4, part = (lane >> 3) & 1, sub = lane & 7;
        #pragma unroll 4
        for (int rr = 0; rr < 32; rr++) {
            int nl = w * 32 + rr;
            const float* src = smemf + nl * 132 + chunk * 64 + sub * 8;
            const float* bp  = bias + c0 + chunk * 64 + sub * 8;
            float4 f0 = *(const float4*)src, f1 = *(const float4*)(src + 4);
            float4 b0 = *(const float4*)bp,  b1 = *(const float4*)(bp + 4);
            float vv[8] = {f0.x + b0.x, f0.y + b0.y, f0.z + b0.z, f0.w + b0.w,
                           f1.x + b1.x, f1.y + b1.y, f1.z + b1.z, f1.w + b1.w};
            unsigned short o8[8];
            #pragma unroll
            for (int e = 0; e < 8; e++) {
                __nv_bfloat16 h = __float2bfloat16(vv[e]);
                if (part) h = __float2bfloat16(vv[e] - __bfloat162float(h));
                o8[e] = __bfloat16_as_ushort(h);
            }
            *(uint4*)(g_vt + ((size_t)batch * NSP + n0 + nl) * CH2
                      + (c0 >> 6) * 128 + chunk * 128 + part * 64 + sub * 8)
                = *(const uint4*)o8;
        }
    }
}

// ---------------- kernel 2: attn = q @ k^T (128x128, 3-term) ----------------
// grid (CH/128=4, CH/128=4, BATCH)
__global__ __launch_bounds__(256, 1) void attn_gemm()
{
    const int batch = blockIdx.z;
    const int c0 = blockIdx.y * 128, d0 = blockIdx.x * 128;

    const __nv_bfloat16* Ag = g_q + ((size_t)batch * CH + c0) * (NSP * 2);
    const __nv_bfloat16* Bg = g_k + ((size_t)batch * CH + d0) * (NSP * 2);

    float acc[4][4][4];
    gemm_core128(Ag, Bg, NSP / 64, NSP * 2, NSP * 2, acc);

    const int tid = threadIdx.x, lane = tid & 31, w = tid >> 5;
    const int wm = (w >> 2) * 64, wn = (w & 3) * 32;

    #pragma unroll
    for (int i = 0; i < 4; i++)
        #pragma unroll
        for (int r2 = 0; r2 < 2; r2++) {
            int m = wm + 16 * i + (lane >> 2) + 8 * r2;
            float* dst = g_attn_raw + ((size_t)batch * CH + c0 + m) * CH + d0;
            #pragma unroll
            for (int j = 0; j < 4; j++) {
                int nl = wn + 8 * j + 2 * (lane & 3);
                *(float2*)(dst + nl) = make_float2(acc[i][j][2 * r2], acc[i][j][2 * r2 + 1]);
            }
        }
}

// ---------------- kernel 3: softmax + hi/lo pack ----------------
__global__ __launch_bounds__(256) void softmax_kernel()
{
    const size_t row = blockIdx.x;
    const float* p = g_attn_raw + row * CH;
    const int tid = threadIdx.x;

    float v0 = p[tid], v1 = p[tid + 256];

    __shared__ float red[8];
    float m = fmaxf(v0, v1);
    #pragma unroll
    for (int o = 16; o > 0; o >>= 1) m = fmaxf(m, __shfl_xor_sync(0xffffffffu, m, o));
    if ((tid & 31) == 0) red[tid >> 5] = m;
    __syncthreads();
    if (tid < 8) {
        float t = red[tid];
        #pragma unroll
        for (int o = 4; o > 0; o >>= 1) t = fmaxf(t, __shfl_xor_sync(0xffu, t, o));
        red[tid] = t;
    }
    __syncthreads();
    m = red[0];

    float e0 = expf(v0 - m), e1 = expf(v1 - m);

    __shared__ float red2[8];
    float s = e0 + e1;
    #pragma unroll
    for (int o = 16; o > 0; o >>= 1) s += __shfl_xor_sync(0xffffffffu, s, o);
    if ((tid & 31) == 0) red2[tid >> 5] = s;
    __syncthreads();
    if (tid < 8) {
        float t = red2[tid];
        #pragma unroll
        for (int o = 4; o > 0; o >>= 1) t += __shfl_xor_sync(0xffu, t, o);
        red2[tid] = t;
    }
    __syncthreads();
    s = red2[0];

    const float inv = 1.0f / s;
    __nv_bfloat16 h, l;
    __nv_bfloat16* dst = g_attn_p + row * CH2;
    int d = tid;
    split2(e0 * inv, h, l);
    dst[(d >> 6) * 128 + (d & 63)]      = h;
    dst[(d >> 6) * 128 + 64 + (d & 63)] = l;
    d = tid + 256;
    split2(e1 * inv, h, l);
    dst[(d >> 6) * 128 + (d & 63)]      = h;
    dst[(d >> 6) * 128 + 64 + (d & 63)] = l;
}

// ---------------- kernel 4: out = attn @ v + x (128x256 tiles) ----------------
// grid (NSP/256=16, CH/128=4, BATCH)
__global__ __launch_bounds__(256, 1) void out_gemm(
    const float* __restrict__ x, float* __restrict__ out)
{
    const int batch = blockIdx.z;
    const int c0 = blockIdx.y * 128, n0 = blockIdx.x * 256;

    const __nv_bfloat16* Ag = g_attn_p + ((size_t)batch * CH + c0) * CH2;
    const __nv_bfloat16* Bg = g_vt + ((size_t)batch * NSP + n0) * CH2;

    float acc[4][8][4];
    gemm_core256(Ag, Bg, CH / 64, CH2, CH2, acc);

    extern __shared__ char smem[];
    float* smemf = (float*)smem;                       // 128 x 260 floats = 133KB
    const int tid = threadIdx.x, lane = tid & 31, w = tid >> 5;
    const int wm = (w >> 2) * 64, wn = (w & 3) * 64;

    #pragma unroll
    for (int i = 0; i < 4; i++)
        #pragma unroll
        for (int j = 0; j < 8; j++)
            #pragma unroll
            for (int r = 0; r < 4; r++) {
                int m = wm + 16 * i + (lane >> 2) + 8 * (r >> 1);
                int n = wn + 8 * j + 2 * (lane & 3) + (r & 1);
                smemf[m * 260 + n] = acc[i][j][r];
            }
    __syncthreads();

    #pragma unroll 4
    for (int rr = 0; rr < 16; rr++) {
        int row = w * 16 + rr;
        size_t off = ((size_t)batch * CH + c0 + row) * NSP + n0;
        #pragma unroll
        for (int half = 0; half < 2; half++) {
            int col = 4 * lane + half * 128;
            float4 a = *(const float4*)(smemf + row * 260 + col);
            float4 xr = *(const float4*)(x + off + col);
            *(float4*)(out + off + col) = make_float4(a.x + xr.x, a.y + xr.y,
                                                      a.z + xr.z, a.w + xr.w);
        }
    }
}

// ---------------- split / pack kernels ----------------
__global__ __launch_bounds__(256) void split_w_kernel(
    const float* __restrict__ wq, const float* __restrict__ wk, const float* __restrict__ wv)
{
    int idx = blockIdx.x * 256 + threadIdx.x;
    int which = idx >> 18;
    int rem = idx & 0x3FFFF;
    int row = rem >> 9, kk = rem & 511;
    const float* wsrc = (which == 0) ? wq : (which == 1) ? wk : wv;
    float f = wsrc[row * CH + kk];
    __nv_bfloat16 h, l; split2(f, h, l);
    __nv_bfloat16* dst = g_w + (size_t)which * CH * CH2 + (size_t)row * CH2
                         + (kk >> 6) * 128 + (kk & 63);
    dst[0] = h; dst[64] = l;
}

// x[b][c][n] -> xt packed rows n, K=c
__global__ __launch_bounds__(256) void split_xt_kernel(const float* __restrict__ x)
{
    __shared__ float t[32][33];
    const int b = blockIdx.z;
    const int n0 = blockIdx.x * 32, c0 = blockIdx.y * 32;
    const int tx = threadIdx.x, ty = threadIdx.y;      // 32 x 8
    #pragma unroll
    for (int i = 0; i < 4; i++) {
        int c = c0 + ty + i * 8;
        t[ty + i * 8][tx] = x[((size_t)b * CH + c) * NSP + n0 + tx];
    }
    __syncthreads();
    #pragma unroll
    for (int i = 0; i < 4; i++) {
        int nl = ty + i * 8;
        float f = t[tx][nl];
        __nv_bfloat16 h, l; split2(f, h, l);
        int c = c0 + tx;
        __nv_bfloat16* dst = g_xt + ((size_t)b * NSP + n0 + nl) * CH2
                             + (c >> 6) * 128 + (c & 63);
        dst[0] = h; dst[64] = l;
    }
}

// ---------------- launch ----------------
extern "C" void kernel_launch(void* const* d_in, const int* in_sizes, int n_in,
                              void* d_out, int out_size) {
    const float* x  = (const float*)d_in[0];
    const float* wq = (const float*)d_in[1];
    const float* bq = (const float*)d_in[2];
    const float* wk = (const float*)d_in[3];
    const float* bk = (const float*)d_in[4];
    const float* wv = (const float*)d_in[5];
    const float* bv = (const float*)d_in[6];
    float* out = (float*)d_out;

    const int SMEM = 196608;   // core256: 2 x 96KB; core128: 3 x 64KB; epilogues <= 135KB
    cudaFuncSetAttribute(qkv_gemm,  cudaFuncAttributeMaxDynamicSharedMemorySize, SMEM);
    cudaFuncSetAttribute(attn_gemm, cudaFuncAttributeMaxDynamicSharedMemorySize, SMEM);
    cudaFuncSetAttribute(out_gemm,  cudaFuncAttributeMaxDynamicSharedMemorySize, SMEM);

    split_w_kernel<<<3 * CH * CH / 256, 256>>>(wq, wk, wv);
    split_xt_kernel<<<dim3(NSP / 32, CH / 32, BATCH), dim3(32, 8)>>>(x);

    qkv_gemm<<<dim3(NSP / 256, CH / 128, BATCH * 3), 256, SMEM>>>(bq, bk, bv);

    attn_gemm<<<dim3(CH / 128, CH / 128, BATCH), 256, SMEM>>>();

    softmax_kernel<<<BATCH * CH, 256>>>();

    out_gemm<<<dim3(NSP / 256, CH / 128, BATCH), 256, SMEM>>>(x, out);
}

// round 12
// speedup vs baseline: 1.3381x; 1.3381x over previous
#include <cuda_runtime.h>
#include <cuda_bf16.h>
#include <cstdint>

#define BATCH 8
#define CH    512
#define NSP   4096
#define CH2   (CH * 2)
#define NSP2  (NSP * 2)

// ---------------- global scratch ----------------
// packed row layout: [k/64 chunk][hi 64 | lo 64] bf16  (128 elems = 256B per chunk)
__device__ __align__(16) __nv_bfloat16 g_w    [(size_t)3 * CH * CH2];      // rows=c, K=c'
__device__ __align__(16) __nv_bfloat16 g_xt   [(size_t)BATCH * NSP * CH2]; // rows=n, K=c
__device__ __align__(16) __nv_bfloat16 g_xr   [(size_t)BATCH * CH * NSP2]; // rows=c, K=n
__device__ __align__(16) __nv_bfloat16 g_vt   [(size_t)BATCH * NSP * CH2]; // rows=n, K=c
__device__ __align__(16) __nv_bfloat16 g_Gp   [(size_t)BATCH * CH * CH2];  // G=XX^T packed
__device__ __align__(16) __nv_bfloat16 g_A1p  [(size_t)BATCH * CH * CH2];  // Wq*G packed
__device__ __align__(16) __nv_bfloat16 g_attn_p[(size_t)BATCH * CH * CH2]; // softmax packed
__device__ __align__(16) float         g_attn_raw[(size_t)BATCH * CH * CH];
__device__ float g_s  [BATCH * CH];        // row sums of X
__device__ float g_tqk[2 * BATCH * CH];    // [0]=Wq*s, [1]=Wk*s

// ---------------- low-level helpers ----------------
__device__ __forceinline__ uint32_t smem_u32(const void* p) {
    uint32_t a;
    asm("{ .reg .u64 t; cvta.to.shared.u64 t, %1; cvt.u32.u64 %0, t; }" : "=r"(a) : "l"(p));
    return a;
}
__device__ __forceinline__ void cp16(uint32_t s, const void* g) {
    asm volatile("cp.async.cg.shared.global [%0], [%1], 16;" :: "r"(s), "l"(g));
}
__device__ __forceinline__ void ldsm4(uint32_t* r, uint32_t addr) {
    asm volatile("ldmatrix.sync.aligned.m8n8.x4.shared.b16 {%0,%1,%2,%3}, [%4];"
                 : "=r"(r[0]), "=r"(r[1]), "=r"(r[2]), "=r"(r[3]) : "r"(addr));
}
__device__ __forceinline__ void mma16816(float* d, const uint32_t* a, const uint32_t* b) {
    asm volatile("mma.sync.aligned.m16n8k16.row.col.f32.bf16.bf16.f32 "
                 "{%0,%1,%2,%3}, {%4,%5,%6,%7}, {%8,%9}, {%0,%1,%2,%3};"
                 : "+f"(d[0]), "+f"(d[1]), "+f"(d[2]), "+f"(d[3])
                 : "r"(a[0]), "r"(a[1]), "r"(a[2]), "r"(a[3]), "r"(b[0]), "r"(b[1]));
}
__device__ __forceinline__ void split2(float f, __nv_bfloat16& h, __nv_bfloat16& l) {
    h = __float2bfloat16(f);
    l = __float2bfloat16(f - __bfloat162float(h));
}

// Load one 128-row x 256B chunk tile (32KB) with XOR-8 swizzle on 16B units.
__device__ __forceinline__ void load_tile(uint32_t sdst, const __nv_bfloat16* gsrc,
                                          size_t rowlen, int tid) {
    #pragma unroll
    for (int i = 0; i < 8; i++) {
        int idx = tid + i * 256;
        int r = idx >> 4, u = idx & 15;
        cp16(sdst + r * 256 + ((u ^ (r & 7)) * 16),
             gsrc + (size_t)r * rowlen + u * 8);
    }
}

// ---------------- GEMM core (R8-proven): C[128][128] += A[128,K]*B[128,K]^T ----------
// 3 terms (hh+hl+lh), 3-stage cp.async pipeline, prefetch before compute.
__device__ __forceinline__ void gemm_core(const __nv_bfloat16* __restrict__ Ag,
                                          const __nv_bfloat16* __restrict__ Bg,
                                          int nch, size_t lda, size_t ldb,
                                          float (&acc)[4][4][4]) {
    extern __shared__ char smem[];
    const uint32_t sb = smem_u32(smem);
    const int tid = threadIdx.x;
    const int lane = tid & 31, w = tid >> 5;
    const int wm = (w >> 2) * 64, wn = (w & 3) * 32;

    #pragma unroll
    for (int i = 0; i < 4; i++)
        #pragma unroll
        for (int j = 0; j < 4; j++)
            #pragma unroll
            for (int r = 0; r < 4; r++) acc[i][j][r] = 0.f;

    load_tile(sb,         Ag, lda, tid);
    load_tile(sb + 32768, Bg, ldb, tid);
    asm volatile("cp.async.commit_group;" ::: "memory");
    if (nch > 1) {
        load_tile(sb + 65536, Ag + 128, lda, tid);
        load_tile(sb + 98304, Bg + 128, ldb, tid);
    }
    asm volatile("cp.async.commit_group;" ::: "memory");

    for (int ch = 0; ch < nch; ch++) {
        asm volatile("cp.async.wait_group 1;" ::: "memory");
        __syncthreads();
        if (ch + 2 < nch) {
            const uint32_t st = sb + ((ch + 2) % 3) * 65536;
            load_tile(st,         Ag + (size_t)(ch + 2) * 128, lda, tid);
            load_tile(st + 32768, Bg + (size_t)(ch + 2) * 128, ldb, tid);
        }
        asm volatile("cp.async.commit_group;" ::: "memory");

        const uint32_t s_a = sb + (ch % 3) * 65536;
        const uint32_t s_b = s_a + 32768;
        #pragma unroll
        for (int ks = 0; ks < 4; ks++) {
            uint32_t ah[4][4], al[4][4], bh[2][4], bl[2][4];
            #pragma unroll
            for (int i = 0; i < 4; i++) {
                int r = wm + 16 * i + (lane & 7) + ((lane >> 3) & 1) * 8;
                int u = 2 * ks + ((lane >> 4) & 1);
                ldsm4(ah[i], s_a + r * 256 + ((u       ^ (r & 7)) * 16));
                ldsm4(al[i], s_a + r * 256 + (((u + 8) ^ (r & 7)) * 16));
            }
            #pragma unroll
            for (int jj = 0; jj < 2; jj++) {
                int r = wn + 16 * jj + (lane & 7) + ((lane >> 4) & 1) * 8;
                int u = 2 * ks + ((lane >> 3) & 1);
                ldsm4(bh[jj], s_b + r * 256 + ((u       ^ (r & 7)) * 16));
                ldsm4(bl[jj], s_b + r * 256 + (((u + 8) ^ (r & 7)) * 16));
            }
            #pragma unroll
            for (int i = 0; i < 4; i++)
                #pragma unroll
                for (int j = 0; j < 4; j++)
                    mma16816(acc[i][j], ah[i], &bh[j >> 1][(j & 1) * 2]);
            #pragma unroll
            for (int i = 0; i < 4; i++)
                #pragma unroll
                for (int j = 0; j < 4; j++)
                    mma16816(acc[i][j], ah[i], &bl[j >> 1][(j & 1) * 2]);
            #pragma unroll
            for (int i = 0; i < 4; i++)
                #pragma unroll
                for (int j = 0; j < 4; j++)
                    mma16816(acc[i][j], al[i], &bh[j >> 1][(j & 1) * 2]);
        }
    }
    asm volatile("cp.async.wait_group 0;" ::: "memory");
    __syncthreads();
}

#define PITCH 132
__device__ __forceinline__ void store_acc(float* smemf, const float (&acc)[4][4][4],
                                          int lane, int wm, int wn, bool transpose) {
    #pragma unroll
    for (int i = 0; i < 4; i++)
        #pragma unroll
        for (int j = 0; j < 4; j++)
            #pragma unroll
            for (int r = 0; r < 4; r++) {
                int m = wm + 16 * i + (lane >> 2) + 8 * (r >> 1);
                int n = wn + 8 * j + 2 * (lane & 3) + (r & 1);
                if (transpose) smemf[n * PITCH + m] = acc[i][j][r];
                else           smemf[m * PITCH + n] = acc[i][j][r];
            }
}

// Packed hi/lo write of a staged 128x128 fp32 tile: rows -> dstbase rows (stride CH2),
// cols -> packed chunk layout at column base already folded into dstbase.
__device__ __forceinline__ void write_packed(const float* smemf, __nv_bfloat16* dstbase,
                                             int w, int lane) {
    const int chunk = lane >> 4, part = (lane >> 3) & 1, sub = lane & 7;
    #pragma unroll 4
    for (int rr = 0; rr < 16; rr++) {
        int row = w * 16 + rr;
        const float* src = smemf + row * PITCH + chunk * 64 + sub * 8;
        float4 f0 = *(const float4*)src, f1 = *(const float4*)(src + 4);
        float vv[8] = {f0.x, f0.y, f0.z, f0.w, f1.x, f1.y, f1.z, f1.w};
        unsigned short o8[8];
        #pragma unroll
        for (int e = 0; e < 8; e++) {
            __nv_bfloat16 h = __float2bfloat16(vv[e]);
            if (part) h = __float2bfloat16(vv[e] - __bfloat162float(h));
            o8[e] = __bfloat16_as_ushort(h);
        }
        *(uint4*)(dstbase + (size_t)row * CH2 + chunk * 128 + part * 64 + sub * 8)
            = *(const uint4*)o8;
    }
}

// ---------------- kernel: G = X X^T (per batch), packed output ----------------
// grid (4, 4, 8)
__global__ __launch_bounds__(256, 1) void g_gemm()
{
    const int batch = blockIdx.z;
    const int c0 = blockIdx.y * 128, d0 = blockIdx.x * 128;
    const __nv_bfloat16* Ag = g_xr + ((size_t)batch * CH + c0) * NSP2;
    const __nv_bfloat16* Bg = g_xr + ((size_t)batch * CH + d0) * NSP2;

    float acc[4][4][4];
    gemm_core(Ag, Bg, NSP / 64, NSP2, NSP2, acc);

    extern __shared__ char smem[];
    float* smemf = (float*)smem;
    const int tid = threadIdx.x, lane = tid & 31, w = tid >> 5;
    store_acc(smemf, acc, lane, (w >> 2) * 64, (w & 3) * 32, false);
    __syncthreads();
    write_packed(smemf, g_Gp + ((size_t)batch * CH + c0) * CH2 + d0 * 2, w, lane);
}

// ---------------- kernel: A1 = Wq * G, packed output ----------------
// grid (4, 4, 8): output tile rows c0, cols e0
__global__ __launch_bounds__(256, 1) void a1_gemm()
{
    const int batch = blockIdx.z;
    const int c0 = blockIdx.y * 128, e0 = blockIdx.x * 128;
    const __nv_bfloat16* Ag = g_w + (size_t)c0 * CH2;                       // Wq rows c
    const __nv_bfloat16* Bg = g_Gp + ((size_t)batch * CH + e0) * CH2;       // G rows e (sym)

    float acc[4][4][4];
    gemm_core(Ag, Bg, CH / 64, CH2, CH2, acc);

    extern __shared__ char smem[];
    float* smemf = (float*)smem;
    const int tid = threadIdx.x, lane = tid & 31, w = tid >> 5;
    store_acc(smemf, acc, lane, (w >> 2) * 64, (w & 3) * 32, false);
    __syncthreads();
    write_packed(smemf, g_A1p + ((size_t)batch * CH + c0) * CH2 + e0 * 2, w, lane);
}

// ---------------- kernel: attn_raw = A1 * Wk^T ----------------
// grid (4, 4, 8)
__global__ __launch_bounds__(256, 1) void attn2_gemm()
{
    const int batch = blockIdx.z;
    const int c0 = blockIdx.y * 128, d0 = blockIdx.x * 128;
    const __nv_bfloat16* Ag = g_A1p + ((size_t)batch * CH + c0) * CH2;
    const __nv_bfloat16* Bg = g_w + (size_t)CH * CH2 + (size_t)d0 * CH2;    // Wk rows d

    float acc[4][4][4];
    gemm_core(Ag, Bg, CH / 64, CH2, CH2, acc);

    const int tid = threadIdx.x, lane = tid & 31, w = tid >> 5;
    const int wm = (w >> 2) * 64, wn = (w & 3) * 32;
    #pragma unroll
    for (int i = 0; i < 4; i++)
        #pragma unroll
        for (int r2 = 0; r2 < 2; r2++) {
            int m = wm + 16 * i + (lane >> 2) + 8 * r2;
            float* dst = g_attn_raw + ((size_t)batch * CH + c0 + m) * CH + d0;
            #pragma unroll
            for (int j = 0; j < 4; j++) {
                int nl = wn + 8 * j + 2 * (lane & 3);
                *(float2*)(dst + nl) = make_float2(acc[i][j][2 * r2], acc[i][j][2 * r2 + 1]);
            }
        }
}

// ---------------- kernel: v projection (Wv * X), vt packed transposed ----------------
// grid (NSP/128=32, CH/128=4, BATCH)
__global__ __launch_bounds__(256, 1) void vproj_gemm(const float* __restrict__ bv)
{
    const int batch = blockIdx.z;
    const int c0 = blockIdx.y * 128, n0 = blockIdx.x * 128;
    const __nv_bfloat16* Ag = g_w + (size_t)2 * CH * CH2 + (size_t)c0 * CH2;
    const __nv_bfloat16* Bg = g_xt + ((size_t)batch * NSP + n0) * CH2;

    float acc[4][4][4];
    gemm_core(Ag, Bg, CH / 64, CH2, CH2, acc);

    extern __shared__ char smem[];
    float* smemf = (float*)smem;
    const int tid = threadIdx.x, lane = tid & 31, w = tid >> 5;
    store_acc(smemf, acc, lane, (w >> 2) * 64, (w & 3) * 32, true);   // transposed: rows=n
    __syncthreads();

    const int chunk = lane >> 4, part = (lane >> 3) & 1, sub = lane & 7;
    #pragma unroll 4
    for (int rr = 0; rr < 16; rr++) {
        int nl = w * 16 + rr;
        const float* src = smemf + nl * PITCH + chunk * 64 + sub * 8;
        const float* bp  = bv + c0 + chunk * 64 + sub * 8;
        float4 f0 = *(const float4*)src, f1 = *(const float4*)(src + 4);
        float4 b0 = *(const float4*)bp,  b1 = *(const float4*)(bp + 4);
        float vv[8] = {f0.x + b0.x, f0.y + b0.y, f0.z + b0.z, f0.w + b0.w,
                       f1.x + b1.x, f1.y + b1.y, f1.z + b1.z, f1.w + b1.w};
        unsigned short o8[8];
        #pragma unroll
        for (int e = 0; e < 8; e++) {
            __nv_bfloat16 h = __float2bfloat16(vv[e]);
            if (part) h = __float2bfloat16(vv[e] - __bfloat162float(h));
            o8[e] = __bfloat16_as_ushort(h);
        }
        *(uint4*)(g_vt + ((size_t)batch * NSP + n0 + nl) * CH2
                  + c0 * 2 + chunk * 128 + part * 64 + sub * 8)
            = *(const uint4*)o8;
    }
}

// ---------------- kernel: softmax with rank-1 bias corrections + hi/lo pack -------
__global__ __launch_bounds__(256) void softmax_kernel(
    const float* __restrict__ bq, const float* __restrict__ bk)
{
    const size_t row = blockIdx.x;
    const int b = (int)(row >> 9), c = (int)(row & 511);
    const float* p = g_attn_raw + row * CH;
    const int tid = threadIdx.x;

    const float tq_c = g_tqk[b * CH + c];
    const float bq_c = bq[c];

    int d0i = tid, d1i = tid + 256;
    float v0 = p[d0i] + tq_c * bk[d0i] + bq_c * g_tqk[BATCH * CH + b * CH + d0i]
             + 4096.0f * bq_c * bk[d0i];
    float v1 = p[d1i] + tq_c * bk[d1i] + bq_c * g_tqk[BATCH * CH + b * CH + d1i]
             + 4096.0f * bq_c * bk[d1i];

    __shared__ float red[8];
    float m = fmaxf(v0, v1);
    #pragma unroll
    for (int o = 16; o > 0; o >>= 1) m = fmaxf(m, __shfl_xor_sync(0xffffffffu, m, o));
    if ((tid & 31) == 0) red[tid >> 5] = m;
    __syncthreads();
    if (tid < 8) {
        float t = red[tid];
        #pragma unroll
        for (int o = 4; o > 0; o >>= 1) t = fmaxf(t, __shfl_xor_sync(0xffu, t, o));
        red[tid] = t;
    }
    __syncthreads();
    m = red[0];

    float e0 = expf(v0 - m), e1 = expf(v1 - m);

    __shared__ float red2[8];
    float s = e0 + e1;
    #pragma unroll
    for (int o = 16; o > 0; o >>= 1) s += __shfl_xor_sync(0xffffffffu, s, o);
    if ((tid & 31) == 0) red2[tid >> 5] = s;
    __syncthreads();
    if (tid < 8) {
        float t = red2[tid];
        #pragma unroll
        for (int o = 4; o > 0; o >>= 1) t += __shfl_xor_sync(0xffu, t, o);
        red2[tid] = t;
    }
    __syncthreads();
    s = red2[0];

    const float inv = 1.0f / s;
    __nv_bfloat16 h, l;
    __nv_bfloat16* dst = g_attn_p + row * CH2;
    int d = tid;
    split2(e0 * inv, h, l);
    dst[(d >> 6) * 128 + (d & 63)]      = h;
    dst[(d >> 6) * 128 + 64 + (d & 63)] = l;
    d = tid + 256;
    split2(e1 * inv, h, l);
    dst[(d >> 6) * 128 + (d & 63)]      = h;
    dst[(d >> 6) * 128 + 64 + (d & 63)] = l;
}

// ---------------- kernel: out = attn_p * vt + x ----------------
// grid (NSP/128=32, CH/128=4, BATCH)
__global__ __launch_bounds__(256, 1) void out_gemm(
    const float* __restrict__ x, float* __restrict__ out)
{
    const int batch = blockIdx.z;
    const int c0 = blockIdx.y * 128, n0 = blockIdx.x * 128;
    const __nv_bfloat16* Ag = g_attn_p + ((size_t)batch * CH + c0) * CH2;
    const __nv_bfloat16* Bg = g_vt + ((size_t)batch * NSP + n0) * CH2;

    float acc[4][4][4];
    gemm_core(Ag, Bg, CH / 64, CH2, CH2, acc);

    extern __shared__ char smem[];
    float* smemf = (float*)smem;
    const int tid = threadIdx.x, lane = tid & 31, w = tid >> 5;
    store_acc(smemf, acc, lane, (w >> 2) * 64, (w & 3) * 32, false);
    __syncthreads();

    #pragma unroll 4
    for (int rr = 0; rr < 16; rr++) {
        int row = w * 16 + rr;
        size_t off = ((size_t)batch * CH + c0 + row) * NSP + n0 + 4 * lane;
        float4 a = *(const float4*)(smemf + row * PITCH + 4 * lane);
        float4 xr = *(const float4*)(x + off);
        *(float4*)(out + off) = make_float4(a.x + xr.x, a.y + xr.y, a.z + xr.z, a.w + xr.w);
    }
}

// ---------------- split / reduction kernels ----------------
__global__ __launch_bounds__(256) void split_w_kernel(
    const float* __restrict__ wq, const float* __restrict__ wk, const float* __restrict__ wv)
{
    int idx = blockIdx.x * 256 + threadIdx.x;
    int which = idx >> 18;
    int rem = idx & 0x3FFFF;
    int row = rem >> 9, kk = rem & 511;
    const float* wsrc = (which == 0) ? wq : (which == 1) ? wk : wv;
    float f = wsrc[row * CH + kk];
    __nv_bfloat16 h, l; split2(f, h, l);
    __nv_bfloat16* dst = g_w + (size_t)which * CH * CH2 + (size_t)row * CH2
                         + (kk >> 6) * 128 + (kk & 63);
    dst[0] = h; dst[64] = l;
}

// x[b][c][n] -> xt[n][PCK(c)] (rows=n) AND xr[c][PCK(n)] (rows=c)
__global__ __launch_bounds__(256) void split_x_kernel(const float* __restrict__ x)
{
    __shared__ float t[32][33];
    const int b = blockIdx.z;
    const int n0 = blockIdx.x * 32, c0 = blockIdx.y * 32;
    const int tx = threadIdx.x, ty = threadIdx.y;      // 32 x 8
    #pragma unroll
    for (int i = 0; i < 4; i++) {
        int c = c0 + ty + i * 8;
        float f = x[((size_t)b * CH + c) * NSP + n0 + tx];
        t[ty + i * 8][tx] = f;
        // xr write: rows=c, coalesced in n
        __nv_bfloat16 h, l; split2(f, h, l);
        int n = n0 + tx;
        __nv_bfloat16* dr = g_xr + ((size_t)b * CH + c) * NSP2
                            + (n >> 6) * 128 + (n & 63);
        dr[0] = h; dr[64] = l;
    }
    __syncthreads();
    #pragma unroll
    for (int i = 0; i < 4; i++) {
        int nl = ty + i * 8;
        float f = t[tx][nl];
        __nv_bfloat16 h, l; split2(f, h, l);
        int c = c0 + tx;
        __nv_bfloat16* dst = g_xt + ((size_t)b * NSP + n0 + nl) * CH2
                             + (c >> 6) * 128 + (c & 63);
        dst[0] = h; dst[64] = l;
    }
}

// s[b][e] = sum_n x[b,e,n]; grid (CH, BATCH), 256 threads
__global__ __launch_bounds__(256) void rowsum_kernel(const float* __restrict__ x)
{
    const int e = blockIdx.x, b = blockIdx.y;
    const float* row = x + ((size_t)b * CH + e) * NSP;
    const int tid = threadIdx.x;
    float sum = 0.f;
    for (int i = tid; i < NSP; i += 256) sum += row[i];
    __shared__ float red[8];
    #pragma unroll
    for (int o = 16; o > 0; o >>= 1) sum += __shfl_xor_sync(0xffffffffu, sum, o);
    if ((tid & 31) == 0) red[tid >> 5] = sum;
    __syncthreads();
    if (tid == 0) {
        float t2 = 0.f;
        #pragma unroll
        for (int i = 0; i < 8; i++) t2 += red[i];
        g_s[b * CH + e] = t2;
    }
}

// tqk[which][b][c] = sum_e W[c,e]*s[b,e]; grid (CH/8=64, BATCH, 2), 256 thr (8 warps)
__global__ __launch_bounds__(256) void tqk_kernel(
    const float* __restrict__ wq, const float* __restrict__ wk)
{
    const int b = blockIdx.y, which = blockIdx.z;
    const int w = threadIdx.x >> 5, lane = threadIdx.x & 31;
    const int c = blockIdx.x * 8 + w;
    const float* W = ((which == 0) ? wq : wk) + (size_t)c * CH;
    const float* s = g_s + b * CH;
    float sum = 0.f;
    for (int e = lane; e < CH; e += 32) sum += W[e] * s[e];
    #pragma unroll
    for (int o = 16; o > 0; o >>= 1) sum += __shfl_xor_sync(0xffffffffu, sum, o);
    if (lane == 0) g_tqk[which * BATCH * CH + b * CH + c] = sum;
}

// ---------------- launch ----------------
extern "C" void kernel_launch(void* const* d_in, const int* in_sizes, int n_in,
                              void* d_out, int out_size) {
    const float* x  = (const float*)d_in[0];
    const float* wq = (const float*)d_in[1];
    const float* bq = (const float*)d_in[2];
    const float* wk = (const float*)d_in[3];
    const float* bk = (const float*)d_in[4];
    const float* wv = (const float*)d_in[5];
    const float* bv = (const float*)d_in[6];
    float* out = (float*)d_out;

    const int SMEM = 196608;   // 3 stages x 64KB; epilogues stage <= 67.6KB
    cudaFuncSetAttribute(g_gemm,     cudaFuncAttributeMaxDynamicSharedMemorySize, SMEM);
    cudaFuncSetAttribute(a1_gemm,    cudaFuncAttributeMaxDynamicSharedMemorySize, SMEM);
    cudaFuncSetAttribute(attn2_gemm, cudaFuncAttributeMaxDynamicSharedMemorySize, SMEM);
    cudaFuncSetAttribute(vproj_gemm, cudaFuncAttributeMaxDynamicSharedMemorySize, SMEM);
    cudaFuncSetAttribute(out_gemm,   cudaFuncAttributeMaxDynamicSharedMemorySize, SMEM);

    split_w_kernel<<<3 * CH * CH / 256, 256>>>(wq, wk, wv);
    split_x_kernel<<<dim3(NSP / 32, CH / 32, BATCH), dim3(32, 8)>>>(x);
    rowsum_kernel<<<dim3(CH, BATCH), 256>>>(x);
    tqk_kernel<<<dim3(CH / 8, BATCH, 2), 256>>>(wq, wk);

    g_gemm<<<dim3(4, 4, BATCH), 256, SMEM>>>();
    a1_gemm<<<dim3(4, 4, BATCH), 256, SMEM>>>();
    attn2_gemm<<<dim3(4, 4, BATCH), 256, SMEM>>>();

    softmax_kernel<<<BATCH * CH, 256>>>(bq, bk);

    vproj_gemm<<<dim3(NSP / 128, CH / 128, BATCH), 256, SMEM>>>(bv);
    out_gemm<<<dim3(NSP / 128, CH / 128, BATCH), 256, SMEM>>>(x, out);
}

// round 13
// speedup vs baseline: 1.5989x; 1.1950x over previous
#include <cuda_runtime.h>
#include <cuda_bf16.h>
#include <cstdint>

#define BATCH 8
#define CH    512
#define NSP   4096
#define CH2   (CH * 2)
#define NSP2  (NSP * 2)

// ---------------- global scratch ----------------
// packed row layout: [k/64 chunk][hi 64 | lo 64] bf16  (128 elems = 256B per chunk)
__device__ __align__(16) __nv_bfloat16 g_w    [(size_t)2 * CH * CH2];      // Wq,Wk rows=c, K=e
__device__ __align__(16) __nv_bfloat16 g_wvT  [(size_t)CH * CH2];          // Wv^T rows=e, K=o
__device__ __align__(16) __nv_bfloat16 g_xt   [(size_t)BATCH * NSP * CH2]; // rows=n, K=c
__device__ __align__(16) __nv_bfloat16 g_xr   [(size_t)BATCH * CH * NSP2]; // rows=c, K=n
__device__ __align__(16) __nv_bfloat16 g_Gp   [(size_t)BATCH * CH * CH2];  // G=XX^T packed
__device__ __align__(16) __nv_bfloat16 g_A1p  [(size_t)BATCH * CH * CH2];  // Wq*G packed
__device__ __align__(16) __nv_bfloat16 g_attn_p[(size_t)BATCH * CH * CH2]; // softmax packed
__device__ __align__(16) __nv_bfloat16 g_Mp   [(size_t)BATCH * CH * CH2];  // attn*Wv packed
__device__ __align__(16) float         g_attn_raw[(size_t)BATCH * CH * CH];
__device__ float g_s  [BATCH * CH];        // row sums of X
__device__ float g_tqk[2 * BATCH * CH];    // [0]=Wq*s, [1]=Wk*s
__device__ float g_av [BATCH * CH];        // attn @ bv

// ---------------- low-level helpers ----------------
__device__ __forceinline__ uint32_t smem_u32(const void* p) {
    uint32_t a;
    asm("{ .reg .u64 t; cvta.to.shared.u64 t, %1; cvt.u32.u64 %0, t; }" : "=r"(a) : "l"(p));
    return a;
}
__device__ __forceinline__ void cp16(uint32_t s, const void* g) {
    asm volatile("cp.async.cg.shared.global [%0], [%1], 16;" :: "r"(s), "l"(g));
}
__device__ __forceinline__ void ldsm4(uint32_t* r, uint32_t addr) {
    asm volatile("ldmatrix.sync.aligned.m8n8.x4.shared.b16 {%0,%1,%2,%3}, [%4];"
                 : "=r"(r[0]), "=r"(r[1]), "=r"(r[2]), "=r"(r[3]) : "r"(addr));
}
__device__ __forceinline__ void mma16816(float* d, const uint32_t* a, const uint32_t* b) {
    asm volatile("mma.sync.aligned.m16n8k16.row.col.f32.bf16.bf16.f32 "
                 "{%0,%1,%2,%3}, {%4,%5,%6,%7}, {%8,%9}, {%0,%1,%2,%3};"
                 : "+f"(d[0]), "+f"(d[1]), "+f"(d[2]), "+f"(d[3])
                 : "r"(a[0]), "r"(a[1]), "r"(a[2]), "r"(a[3]), "r"(b[0]), "r"(b[1]));
}
__device__ __forceinline__ void split2(float f, __nv_bfloat16& h, __nv_bfloat16& l) {
    h = __float2bfloat16(f);
    l = __float2bfloat16(f - __bfloat162float(h));
}

// Load one 128-row x 256B chunk tile (32KB) with XOR-8 swizzle on 16B units.
__device__ __forceinline__ void load_tile(uint32_t sdst, const __nv_bfloat16* gsrc,
                                          size_t rowlen, int tid) {
    #pragma unroll
    for (int i = 0; i < 8; i++) {
        int idx = tid + i * 256;
        int r = idx >> 4, u = idx & 15;
        cp16(sdst + r * 256 + ((u ^ (r & 7)) * 16),
             gsrc + (size_t)r * rowlen + u * 8);
    }
}

// ---------------- GEMM core (proven): C[128][128] += A[128,K]*B[128,K]^T ----------
__device__ __forceinline__ void gemm_core(const __nv_bfloat16* __restrict__ Ag,
                                          const __nv_bfloat16* __restrict__ Bg,
                                          int nch, size_t lda, size_t ldb,
                                          float (&acc)[4][4][4]) {
    extern __shared__ char smem[];
    const uint32_t sb = smem_u32(smem);
    const int tid = threadIdx.x;
    const int lane = tid & 31, w = tid >> 5;
    const int wm = (w >> 2) * 64, wn = (w & 3) * 32;

    #pragma unroll
    for (int i = 0; i < 4; i++)
        #pragma unroll
        for (int j = 0; j < 4; j++)
            #pragma unroll
            for (int r = 0; r < 4; r++) acc[i][j][r] = 0.f;

    load_tile(sb,         Ag, lda, tid);
    load_tile(sb + 32768, Bg, ldb, tid);
    asm volatile("cp.async.commit_group;" ::: "memory");
    if (nch > 1) {
        load_tile(sb + 65536, Ag + 128, lda, tid);
        load_tile(sb + 98304, Bg + 128, ldb, tid);
    }
    asm volatile("cp.async.commit_group;" ::: "memory");

    for (int ch = 0; ch < nch; ch++) {
        asm volatile("cp.async.wait_group 1;" ::: "memory");
        __syncthreads();
        if (ch + 2 < nch) {
            const uint32_t st = sb + ((ch + 2) % 3) * 65536;
            load_tile(st,         Ag + (size_t)(ch + 2) * 128, lda, tid);
            load_tile(st + 32768, Bg + (size_t)(ch + 2) * 128, ldb, tid);
        }
        asm volatile("cp.async.commit_group;" ::: "memory");

        const uint32_t s_a = sb + (ch % 3) * 65536;
        const uint32_t s_b = s_a + 32768;
        #pragma unroll
        for (int ks = 0; ks < 4; ks++) {
            uint32_t ah[4][4], al[4][4], bh[2][4], bl[2][4];
            #pragma unroll
            for (int i = 0; i < 4; i++) {
                int r = wm + 16 * i + (lane & 7) + ((lane >> 3) & 1) * 8;
                int u = 2 * ks + ((lane >> 4) & 1);
                ldsm4(ah[i], s_a + r * 256 + ((u       ^ (r & 7)) * 16));
                ldsm4(al[i], s_a + r * 256 + (((u + 8) ^ (r & 7)) * 16));
            }
            #pragma unroll
            for (int jj = 0; jj < 2; jj++) {
                int r = wn + 16 * jj + (lane & 7) + ((lane >> 4) & 1) * 8;
                int u = 2 * ks + ((lane >> 3) & 1);
                ldsm4(bh[jj], s_b + r * 256 + ((u       ^ (r & 7)) * 16));
                ldsm4(bl[jj], s_b + r * 256 + (((u + 8) ^ (r & 7)) * 16));
            }
            #pragma unroll
            for (int i = 0; i < 4; i++)
                #pragma unroll
                for (int j = 0; j < 4; j++)
                    mma16816(acc[i][j], ah[i], &bh[j >> 1][(j & 1) * 2]);
            #pragma unroll
            for (int i = 0; i < 4; i++)
                #pragma unroll
                for (int j = 0; j < 4; j++)
                    mma16816(acc[i][j], ah[i], &bl[j >> 1][(j & 1) * 2]);
            #pragma unroll
            for (int i = 0; i < 4; i++)
                #pragma unroll
                for (int j = 0; j < 4; j++)
                    mma16816(acc[i][j], al[i], &bh[j >> 1][(j & 1) * 2]);
        }
    }
    asm volatile("cp.async.wait_group 0;" ::: "memory");
    __syncthreads();
}

#define PITCH 132
__device__ __forceinline__ void store_acc(float* smemf, const float (&acc)[4][4][4],
                                          int lane, int wm, int wn, bool transpose) {
    #pragma unroll
    for (int i = 0; i < 4; i++)
        #pragma unroll
        for (int j = 0; j < 4; j++)
            #pragma unroll
            for (int r = 0; r < 4; r++) {
                int m = wm + 16 * i + (lane >> 2) + 8 * (r >> 1);
                int n = wn + 8 * j + 2 * (lane & 3) + (r & 1);
                if (transpose) smemf[n * PITCH + m] = acc[i][j][r];
                else           smemf[m * PITCH + n] = acc[i][j][r];
            }
}

// Packed hi/lo write of staged 128x128 fp32 tile to rows of stride CH2.
__device__ __forceinline__ void write_packed(const float* smemf, __nv_bfloat16* dstbase,
                                             int w, int lane) {
    const int chunk = lane >> 4, part = (lane >> 3) & 1, sub = lane & 7;
    #pragma unroll 4
    for (int rr = 0; rr < 16; rr++) {
        int row = w * 16 + rr;
        const float* src = smemf + row * PITCH + chunk * 64 + sub * 8;
        float4 f0 = *(const float4*)src, f1 = *(const float4*)(src + 4);
        float vv[8] = {f0.x, f0.y, f0.z, f0.w, f1.x, f1.y, f1.z, f1.w};
        unsigned short o8[8];
        #pragma unroll
        for (int e = 0; e < 8; e++) {
            __nv_bfloat16 h = __float2bfloat16(vv[e]);
            if (part) h = __float2bfloat16(vv[e] - __bfloat162float(h));
            o8[e] = __bfloat16_as_ushort(h);
        }
        *(uint4*)(dstbase + (size_t)row * CH2 + chunk * 128 + part * 64 + sub * 8)
            = *(const uint4*)o8;
    }
}

// ---------------- kernel: G = X X^T, symmetric — upper tiles only ----------------
// grid (10, 1, 8): tile list over (ti<=tj)
__global__ __launch_bounds__(256, 1) void g_gemm_sym()
{
    const int ti_tab[10] = {0,0,0,0,1,1,1,2,2,3};
    const int tj_tab[10] = {0,1,2,3,1,2,3,2,3,3};
    const int batch = blockIdx.z;
    const int c0 = ti_tab[blockIdx.x] * 128, d0 = tj_tab[blockIdx.x] * 128;
    const __nv_bfloat16* Ag = g_xr + ((size_t)batch * CH + c0) * NSP2;
    const __nv_bfloat16* Bg = g_xr + ((size_t)batch * CH + d0) * NSP2;

    float acc[4][4][4];
    gemm_core(Ag, Bg, NSP / 64, NSP2, NSP2, acc);

    extern __shared__ char smem[];
    float* smemf = (float*)smem;
    const int tid = threadIdx.x, lane = tid & 31, w = tid >> 5;
    const int wm = (w >> 2) * 64, wn = (w & 3) * 32;

    store_acc(smemf, acc, lane, wm, wn, false);
    __syncthreads();
    write_packed(smemf, g_Gp + ((size_t)batch * CH + c0) * CH2 + d0 * 2, w, lane);
    if (c0 != d0) {
        __syncthreads();
        store_acc(smemf, acc, lane, wm, wn, true);   // transposed tile
        __syncthreads();
        write_packed(smemf, g_Gp + ((size_t)batch * CH + d0) * CH2 + c0 * 2, w, lane);
    }
}

// ---------------- kernel: A1 = Wq * G ----------------
__global__ __launch_bounds__(256, 1) void a1_gemm()
{
    const int batch = blockIdx.z;
    const int c0 = blockIdx.y * 128, e0 = blockIdx.x * 128;
    const __nv_bfloat16* Ag = g_w + (size_t)c0 * CH2;                       // Wq rows c
    const __nv_bfloat16* Bg = g_Gp + ((size_t)batch * CH + e0) * CH2;       // G rows e (sym)

    float acc[4][4][4];
    gemm_core(Ag, Bg, CH / 64, CH2, CH2, acc);

    extern __shared__ char smem[];
    float* smemf = (float*)smem;
    const int tid = threadIdx.x, lane = tid & 31, w = tid >> 5;
    store_acc(smemf, acc, lane, (w >> 2) * 64, (w & 3) * 32, false);
    __syncthreads();
    write_packed(smemf, g_A1p + ((size_t)batch * CH + c0) * CH2 + e0 * 2, w, lane);
}

// ---------------- kernel: attn_raw = A1 * Wk^T ----------------
__global__ __launch_bounds__(256, 1) void attn2_gemm()
{
    const int batch = blockIdx.z;
    const int c0 = blockIdx.y * 128, d0 = blockIdx.x * 128;
    const __nv_bfloat16* Ag = g_A1p + ((size_t)batch * CH + c0) * CH2;
    const __nv_bfloat16* Bg = g_w + (size_t)CH * CH2 + (size_t)d0 * CH2;    // Wk rows d

    float acc[4][4][4];
    gemm_core(Ag, Bg, CH / 64, CH2, CH2, acc);

    const int tid = threadIdx.x, lane = tid & 31, w = tid >> 5;
    const int wm = (w >> 2) * 64, wn = (w & 3) * 32;
    #pragma unroll
    for (int i = 0; i < 4; i++)
        #pragma unroll
        for (int r2 = 0; r2 < 2; r2++) {
            int m = wm + 16 * i + (lane >> 2) + 8 * r2;
            float* dst = g_attn_raw + ((size_t)batch * CH + c0 + m) * CH + d0;
            #pragma unroll
            for (int j = 0; j < 4; j++) {
                int nl = wn + 8 * j + 2 * (lane & 3);
                *(float2*)(dst + nl) = make_float2(acc[i][j][2 * r2], acc[i][j][2 * r2 + 1]);
            }
        }
}

// ---------------- kernel: softmax + rank-1 bias corrections + av + pack ----------
__global__ __launch_bounds__(256) void softmax_kernel(
    const float* __restrict__ bq, const float* __restrict__ bk, const float* __restrict__ bv)
{
    const size_t row = blockIdx.x;
    const int b = (int)(row >> 9), c = (int)(row & 511);
    const float* p = g_attn_raw + row * CH;
    const int tid = threadIdx.x;

    const float tq_c = g_tqk[b * CH + c];
    const float bq_c = bq[c];

    int d0i = tid, d1i = tid + 256;
    float v0 = p[d0i] + tq_c * bk[d0i] + bq_c * g_tqk[BATCH * CH + b * CH + d0i]
             + 4096.0f * bq_c * bk[d0i];
    float v1 = p[d1i] + tq_c * bk[d1i] + bq_c * g_tqk[BATCH * CH + b * CH + d1i]
             + 4096.0f * bq_c * bk[d1i];

    __shared__ float red[8];
    float m = fmaxf(v0, v1);
    #pragma unroll
    for (int o = 16; o > 0; o >>= 1) m = fmaxf(m, __shfl_xor_sync(0xffffffffu, m, o));
    if ((tid & 31) == 0) red[tid >> 5] = m;
    __syncthreads();
    if (tid < 8) {
        float t = red[tid];
        #pragma unroll
        for (int o = 4; o > 0; o >>= 1) t = fmaxf(t, __shfl_xor_sync(0xffu, t, o));
        red[tid] = t;
    }
    __syncthreads();
    m = red[0];

    float e0 = expf(v0 - m), e1 = expf(v1 - m);

    // joint reduce: s = sum(e), av = sum(e * bv)
    __shared__ float red2[8], red3[8];
    float s = e0 + e1;
    float a = e0 * bv[d0i] + e1 * bv[d1i];
    #pragma unroll
    for (int o = 16; o > 0; o >>= 1) {
        s += __shfl_xor_sync(0xffffffffu, s, o);
        a += __shfl_xor_sync(0xffffffffu, a, o);
    }
    if ((tid & 31) == 0) { red2[tid >> 5] = s; red3[tid >> 5] = a; }
    __syncthreads();
    if (tid < 8) {
        float t = red2[tid], u = red3[tid];
        #pragma unroll
        for (int o = 4; o > 0; o >>= 1) {
            t += __shfl_xor_sync(0xffu, t, o);
            u += __shfl_xor_sync(0xffu, u, o);
        }
        red2[tid] = t; red3[tid] = u;
    }
    __syncthreads();
    s = red2[0];

    const float inv = 1.0f / s;
    if (tid == 0) g_av[row] = red3[0] * inv;

    __nv_bfloat16 h, l;
    __nv_bfloat16* dst = g_attn_p + row * CH2;
    int d = tid;
    split2(e0 * inv, h, l);
    dst[(d >> 6) * 128 + (d & 63)]      = h;
    dst[(d >> 6) * 128 + 64 + (d & 63)] = l;
    d = tid + 256;
    split2(e1 * inv, h, l);
    dst[(d >> 6) * 128 + (d & 63)]      = h;
    dst[(d >> 6) * 128 + 64 + (d & 63)] = l;
}

// ---------------- kernel: M = attn * Wv ----------------
// grid (4, 4, 8)
__global__ __launch_bounds__(256, 1) void m_gemm()
{
    const int batch = blockIdx.z;
    const int c0 = blockIdx.y * 128, e0 = blockIdx.x * 128;
    const __nv_bfloat16* Ag = g_attn_p + ((size_t)batch * CH + c0) * CH2;   // rows=c, K=o
    const __nv_bfloat16* Bg = g_wvT + (size_t)e0 * CH2;                     // rows=e, K=o

    float acc[4][4][4];
    gemm_core(Ag, Bg, CH / 64, CH2, CH2, acc);

    extern __shared__ char smem[];
    float* smemf = (float*)smem;
    const int tid = threadIdx.x, lane = tid & 31, w = tid >> 5;
    store_acc(smemf, acc, lane, (w >> 2) * 64, (w & 3) * 32, false);
    __syncthreads();
    write_packed(smemf, g_Mp + ((size_t)batch * CH + c0) * CH2 + e0 * 2, w, lane);
}

// ---------------- kernel: out = M * X + av + x ----------------
// grid (NSP/128=32, CH/128=4, BATCH)
__global__ __launch_bounds__(256, 1) void out_gemm(
    const float* __restrict__ x, float* __restrict__ out)
{
    const int batch = blockIdx.z;
    const int c0 = blockIdx.y * 128, n0 = blockIdx.x * 128;
    const __nv_bfloat16* Ag = g_Mp + ((size_t)batch * CH + c0) * CH2;
    const __nv_bfloat16* Bg = g_xt + ((size_t)batch * NSP + n0) * CH2;

    float acc[4][4][4];
    gemm_core(Ag, Bg, CH / 64, CH2, CH2, acc);

    extern __shared__ char smem[];
    float* smemf = (float*)smem;
    const int tid = threadIdx.x, lane = tid & 31, w = tid >> 5;
    store_acc(smemf, acc, lane, (w >> 2) * 64, (w & 3) * 32, false);
    __syncthreads();

    #pragma unroll 4
    for (int rr = 0; rr < 16; rr++) {
        int row = w * 16 + rr;
        float av = g_av[(size_t)batch * CH + c0 + row];
        size_t off = ((size_t)batch * CH + c0 + row) * NSP + n0 + 4 * lane;
        float4 a = *(const float4*)(smemf + row * PITCH + 4 * lane);
        float4 xr = *(const float4*)(x + off);
        *(float4*)(out + off) = make_float4(a.x + av + xr.x, a.y + av + xr.y,
                                            a.z + av + xr.z, a.w + av + xr.w);
    }
}

// ---------------- split / reduction kernels ----------------
__global__ __launch_bounds__(256) void split_w_kernel(
    const float* __restrict__ wq, const float* __restrict__ wk)
{
    int idx = blockIdx.x * 256 + threadIdx.x;          // 0 .. 2*512*512-1
    int which = idx >> 18;
    int rem = idx & 0x3FFFF;
    int row = rem >> 9, kk = rem & 511;
    const float* wsrc = (which == 0) ? wq : wk;
    float f = wsrc[row * CH + kk];
    __nv_bfloat16 h, l; split2(f, h, l);
    __nv_bfloat16* dst = g_w + (size_t)which * CH * CH2 + (size_t)row * CH2
                         + (kk >> 6) * 128 + (kk & 63);
    dst[0] = h; dst[64] = l;
}

// Wv[o][e] -> wvT[e][PCK(o)] (transposed pack)
__global__ __launch_bounds__(256) void split_wvt_kernel(const float* __restrict__ wv)
{
    __shared__ float t[32][33];
    const int e0 = blockIdx.x * 32, o0 = blockIdx.y * 32;
    const int tx = threadIdx.x, ty = threadIdx.y;      // 32 x 8
    #pragma unroll
    for (int i = 0; i < 4; i++)
        t[ty + i * 8][tx] = wv[(size_t)(o0 + ty + i * 8) * CH + e0 + tx];  // t[o_l][e_l]
    __syncthreads();
    #pragma unroll
    for (int i = 0; i < 4; i++) {
        int el = ty + i * 8;
        float f = t[tx][el];
        __nv_bfloat16 h, l; split2(f, h, l);
        int o = o0 + tx;
        __nv_bfloat16* dst = g_wvT + (size_t)(e0 + el) * CH2 + (o >> 6) * 128 + (o & 63);
        dst[0] = h; dst[64] = l;
    }
}

// x[b][c][n] -> xt[n][PCK(c)] (rows=n) AND xr[c][PCK(n)] (rows=c)
__global__ __launch_bounds__(256) void split_x_kernel(const float* __restrict__ x)
{
    __shared__ float t[32][33];
    const int b = blockIdx.z;
    const int n0 = blockIdx.x * 32, c0 = blockIdx.y * 32;
    const int tx = threadIdx.x, ty = threadIdx.y;      // 32 x 8
    #pragma unroll
    for (int i = 0; i < 4; i++) {
        int c = c0 + ty + i * 8;
        float f = x[((size_t)b * CH + c) * NSP + n0 + tx];
        t[ty + i * 8][tx] = f;
        __nv_bfloat16 h, l; split2(f, h, l);
        int n = n0 + tx;
        __nv_bfloat16* dr = g_xr + ((size_t)b * CH + c) * NSP2
                            + (n >> 6) * 128 + (n & 63);
        dr[0] = h; dr[64] = l;
    }
    __syncthreads();
    #pragma unroll
    for (int i = 0; i < 4; i++) {
        int nl = ty + i * 8;
        float f = t[tx][nl];
        __nv_bfloat16 h, l; split2(f, h, l);
        int c = c0 + tx;
        __nv_bfloat16* dst = g_xt + ((size_t)b * NSP + n0 + nl) * CH2
                             + (c >> 6) * 128 + (c & 63);
        dst[0] = h; dst[64] = l;
    }
}

// s[b][e] = sum_n x[b,e,n]; grid (CH, BATCH)
__global__ __launch_bounds__(256) void rowsum_kernel(const float* __restrict__ x)
{
    const int e = blockIdx.x, b = blockIdx.y;
    const float* row = x + ((size_t)b * CH + e) * NSP;
    const int tid = threadIdx.x;
    float sum = 0.f;
    for (int i = tid; i < NSP; i += 256) sum += row[i];
    __shared__ float red[8];
    #pragma unroll
    for (int o = 16; o > 0; o >>= 1) sum += __shfl_xor_sync(0xffffffffu, sum, o);
    if ((tid & 31) == 0) red[tid >> 5] = sum;
    __syncthreads();
    if (tid == 0) {
        float t2 = 0.f;
        #pragma unroll
        for (int i = 0; i < 8; i++) t2 += red[i];
        g_s[b * CH + e] = t2;
    }
}

// tqk[which][b][c] = sum_e W[c,e]*s[b,e]; grid (CH/8, BATCH, 2)
__global__ __launch_bounds__(256) void tqk_kernel(
    const float* __restrict__ wq, const float* __restrict__ wk)
{
    const int b = blockIdx.y, which = blockIdx.z;
    const int w = threadIdx.x >> 5, lane = threadIdx.x & 31;
    const int c = blockIdx.x * 8 + w;
    const float* W = ((which == 0) ? wq : wk) + (size_t)c * CH;
    const float* s = g_s + b * CH;
    float sum = 0.f;
    for (int e = lane; e < CH; e += 32) sum += W[e] * s[e];
    #pragma unroll
    for (int o = 16; o > 0; o >>= 1) sum += __shfl_xor_sync(0xffffffffu, sum, o);
    if (lane == 0) g_tqk[which * BATCH * CH + b * CH + c] = sum;
}

// ---------------- launch ----------------
extern "C" void kernel_launch(void* const* d_in, const int* in_sizes, int n_in,
                              void* d_out, int out_size) {
    const float* x  = (const float*)d_in[0];
    const float* wq = (const float*)d_in[1];
    const float* bq = (const float*)d_in[2];
    const float* wk = (const float*)d_in[3];
    const float* bk = (const float*)d_in[4];
    const float* wv = (const float*)d_in[5];
    const float* bv = (const float*)d_in[6];
    float* out = (float*)d_out;

    const int SMEM = 196608;   // 3 stages x 64KB; epilogue stage 67.6KB
    cudaFuncSetAttribute(g_gemm_sym, cudaFuncAttributeMaxDynamicSharedMemorySize, SMEM);
    cudaFuncSetAttribute(a1_gemm,    cudaFuncAttributeMaxDynamicSharedMemorySize, SMEM);
    cudaFuncSetAttribute(attn2_gemm, cudaFuncAttributeMaxDynamicSharedMemorySize, SMEM);
    cudaFuncSetAttribute(m_gemm,     cudaFuncAttributeMaxDynamicSharedMemorySize, SMEM);
    cudaFuncSetAttribute(out_gemm,   cudaFuncAttributeMaxDynamicSharedMemorySize, SMEM);

    split_w_kernel<<<2 * CH * CH / 256, 256>>>(wq, wk);
    split_wvt_kernel<<<dim3(CH / 32, CH / 32), dim3(32, 8)>>>(wv);
    split_x_kernel<<<dim3(NSP / 32, CH / 32, BATCH), dim3(32, 8)>>>(x);
    rowsum_kernel<<<dim3(CH, BATCH), 256>>>(x);
    tqk_kernel<<<dim3(CH / 8, BATCH, 2), 256>>>(wq, wk);

    g_gemm_sym<<<dim3(10, 1, BATCH), 256, SMEM>>>();
    a1_gemm<<<dim3(4, 4, BATCH), 256, SMEM>>>();
    attn2_gemm<<<dim3(4, 4, BATCH), 256, SMEM>>>();

    softmax_kernel<<<BATCH * CH, 256>>>(bq, bk, bv);

    m_gemm<<<dim3(4, 4, BATCH), 256, SMEM>>>();
    out_gemm<<<dim3(NSP / 128, CH / 128, BATCH), 256, SMEM>>>(x, out);
}